// round 4
// baseline (speedup 1.0000x reference)
#include <cuda_runtime.h>
#include <math.h>

// Problem constants: x[8, 256, 128, 128] fp32
#define NPLANES 2048          // B*C
#define HW      16384         // 128*128
#define SM_STRIDE 132         // padded row stride (float4-aligned)
#define SM_ROWS   130         // 128 + top/bottom halo
#define SM_FLOATS (SM_ROWS * SM_STRIDE)   // 17160 floats = 68640 B

// Scratch (no allocations allowed)
__device__ float g_p[NPLANES];   // per-plane mean
__device__ float g_a[NPLANES];   // sigmoid attention scales

// ---------------------------------------------------------------------------
// K1: per-(b,c) plane mean. 2048 blocks x 256 threads, float4 loads.
// ---------------------------------------------------------------------------
__global__ void __launch_bounds__(256) mean_kernel(const float* __restrict__ x) {
    int plane = blockIdx.x;
    const float4* xp = (const float4*)(x + (size_t)plane * HW);
    int tid = threadIdx.x;
    float s = 0.f;
#pragma unroll
    for (int k = 0; k < 16; k++) {
        float4 v = xp[tid + k * 256];
        s += (v.x + v.y) + (v.z + v.w);
    }
#pragma unroll
    for (int o = 16; o; o >>= 1) s += __shfl_xor_sync(0xffffffffu, s, o);
    __shared__ float red[8];
    if ((tid & 31) == 0) red[tid >> 5] = s;
    __syncthreads();
    if (tid == 0) {
        float t = 0.f;
#pragma unroll
        for (int i = 0; i < 8; i++) t += red[i];
        g_p[plane] = t * (1.0f / 16384.0f);
    }
}

// ---------------------------------------------------------------------------
// K2 (fused): h = leaky(p @ w1^T); a = sigmoid(h @ w2^T). One block per batch.
// w1: [64,256] row-major, w2: [256,64] row-major.
// ---------------------------------------------------------------------------
__global__ void __launch_bounds__(256) attn_kernel(const float* __restrict__ w1,
                                                    const float* __restrict__ w2) {
    int b = blockIdx.x;
    __shared__ float ps[256];
    __shared__ float hs[64];
    int tid = threadIdx.x;
    ps[tid] = g_p[b * 256 + tid];
    __syncthreads();

    // Phase 1: 4 threads per hidden unit j
    {
        int j = tid >> 2, part = tid & 3;
        const float* wr = w1 + j * 256 + part * 64;
        const float* pr = ps + part * 64;
        float s = 0.f;
#pragma unroll
        for (int c = 0; c < 64; c++) s = fmaf(pr[c], wr[c], s);
        s += __shfl_xor_sync(0xffffffffu, s, 1);
        s += __shfl_xor_sync(0xffffffffu, s, 2);
        if (part == 0) hs[j] = (s > 0.f) ? s : 0.01f * s;
    }
    __syncthreads();

    // Phase 2: one thread per output channel
    {
        const float* wr = w2 + tid * 64;
        float s = 0.f;
#pragma unroll
        for (int j = 0; j < 64; j++) s = fmaf(hs[j], wr[j], s);
        g_a[b * 256 + tid] = 1.0f / (1.0f + expf(-s));
    }
}

// ---------------------------------------------------------------------------
// K3: per-plane fused  scale -> depthwise 3x3 conv (+bias) -> InstanceNorm ->
// leaky_relu. One block per (b,c) plane.
//
// In-place smem: output rows 8k..8k+7 (step k) are written into tile rows
// 8k..8k+7, which hold input rows 8k-1..8k+6 — all dead after this step's
// reads (last reader of input row r-1 is output row r). Later steps read
// tile rows >= 8k+8, so one barrier per step is sufficient. This removes the
// 64-register yv[] array, letting 3 blocks/SM fit the register file.
// ---------------------------------------------------------------------------
__global__ void __launch_bounds__(256, 3) main_kernel(const float* __restrict__ x,
                                                       const float* __restrict__ rw,
                                                       const float* __restrict__ rb,
                                                       float* __restrict__ out) {
    extern __shared__ float sm[];
    int bc = blockIdx.x;
    int c = bc & 255;
    int tid = threadIdx.x;
    float a = g_a[bc];

    // Zero the padded tile (SAME zero-padding at the borders)
    float4* smv = (float4*)sm;
    for (int k = tid; k < SM_FLOATS / 4; k += 256)
        smv[k] = make_float4(0.f, 0.f, 0.f, 0.f);
    __syncthreads();

    // Load plane (float4) scaled by attention, into smem at (+1,+1) offset
    const float4* xp = (const float4*)(x + (size_t)bc * HW);
#pragma unroll
    for (int k = 0; k < 16; k++) {
        int fi = tid + k * 256;        // float4 index within plane
        float4 v = xp[fi];
        int row = fi >> 5;             // 32 float4 per row
        int col = (fi & 31) * 4;
        float* d = sm + (row + 1) * SM_STRIDE + col + 1;
        d[0] = v.x * a; d[1] = v.y * a; d[2] = v.z * a; d[3] = v.w * a;
    }

    float w[9];
#pragma unroll
    for (int i = 0; i < 9; i++) w[i] = rw[c * 9 + i];
    float bias = rb[c];
    __syncthreads();

    // Pass 1: conv + stats, writing outputs in-place (shifted up one tile row)
    float ssum = 0.f, ssq = 0.f;
#pragma unroll
    for (int k = 0; k < 16; k++) {
        int g = tid + k * 256;
        int r = g >> 5;                // output row, in 8k..8k+7
        int c0 = (g & 31) * 4;
        const float* base = sm + r * SM_STRIDE + c0;  // tile rows r..r+2
        float e[3][6];
#pragma unroll
        for (int kh = 0; kh < 3; kh++) {
            float4 q = *(const float4*)(base + kh * SM_STRIDE);
            float2 t = *(const float2*)(base + kh * SM_STRIDE + 4);
            e[kh][0] = q.x; e[kh][1] = q.y; e[kh][2] = q.z;
            e[kh][3] = q.w; e[kh][4] = t.x; e[kh][5] = t.y;
        }
        float4 yq;
        float* yp = (float*)&yq;
#pragma unroll
        for (int j = 0; j < 4; j++) {
            float s = bias;
#pragma unroll
            for (int kh = 0; kh < 3; kh++)
#pragma unroll
                for (int kw = 0; kw < 3; kw++)
                    s = fmaf(e[kh][j + kw], w[kh * 3 + kw], s);
            yp[j] = s;
            ssum += s;
            ssq = fmaf(s, s, ssq);
        }
        __syncthreads();   // all reads of tile rows 8k..8k+9 complete
        // write output row r into tile row r (aligned, dead slot)
        *(float4*)(sm + r * SM_STRIDE + c0) = yq;
    }

    // Block reduction of sum / sumsq
#pragma unroll
    for (int o = 16; o; o >>= 1) {
        ssum += __shfl_xor_sync(0xffffffffu, ssum, o);
        ssq  += __shfl_xor_sync(0xffffffffu, ssq, o);
    }
    __shared__ float r1[8], r2[8];
    __shared__ float s_mu, s_rs;
    if ((tid & 31) == 0) { r1[tid >> 5] = ssum; r2[tid >> 5] = ssq; }
    __syncthreads();
    if (tid == 0) {
        float t1 = 0.f, t2 = 0.f;
#pragma unroll
        for (int i = 0; i < 8; i++) { t1 += r1[i]; t2 += r2[i]; }
        float mu = t1 * (1.0f / 16384.0f);
        float var = t2 * (1.0f / 16384.0f) - mu * mu;
        s_mu = mu;
        s_rs = rsqrtf(var + 1e-5f);
    }
    __syncthreads();
    float mu = s_mu, rs = s_rs;

    // Pass 2: read back own outputs, normalize + leaky relu, float4 stores
    float4* op = (float4*)(out + (size_t)bc * HW);
#pragma unroll
    for (int k = 0; k < 16; k++) {
        int g = tid + k * 256;
        int r = g >> 5;
        int c0 = (g & 31) * 4;
        float4 v = *(const float4*)(sm + r * SM_STRIDE + c0);
        float* vp = (float*)&v;
#pragma unroll
        for (int j = 0; j < 4; j++) {
            float t = (vp[j] - mu) * rs;
            vp[j] = (t > 0.f) ? t : 0.01f * t;
        }
        op[g] = v;
    }
}

// ---------------------------------------------------------------------------
extern "C" void kernel_launch(void* const* d_in, const int* in_sizes, int n_in,
                              void* d_out, int out_size) {
    const float* x  = (const float*)d_in[0];
    const float* w1 = (const float*)d_in[1];   // [64, 256]
    const float* w2 = (const float*)d_in[2];   // [256, 64]
    const float* rw = (const float*)d_in[3];   // [256, 1, 3, 3]
    const float* rb = (const float*)d_in[4];   // [256]
    float* out = (float*)d_out;

    cudaFuncSetAttribute(main_kernel, cudaFuncAttributeMaxDynamicSharedMemorySize,
                         SM_FLOATS * (int)sizeof(float));

    mean_kernel<<<NPLANES, 256>>>(x);
    attn_kernel<<<8, 256>>>(w1, w2);
    main_kernel<<<NPLANES, 256, SM_FLOATS * sizeof(float)>>>(x, rw, rb, out);
}

// round 5
// speedup vs baseline: 1.1906x; 1.1906x over previous
#include <cuda_runtime.h>
#include <math.h>

// Problem constants: x[8, 256, 128, 128] fp32
#define NPLANES 2048          // B*C
#define HW      16384         // 128*128
#define SMS     132           // padded row stride (float4-aligned)
#define SM_ROWS 130           // 128 + top/bottom halo
#define SM_FLOATS (SM_ROWS * SMS)   // 17160 floats = 68640 B

// Scratch (no allocations allowed)
__device__ float g_p[NPLANES];   // per-plane mean
__device__ float g_a[NPLANES];   // sigmoid attention scales

// ---------------------------------------------------------------------------
// K1: per-(b,c) plane mean. 2048 blocks x 256 threads, float4 loads.
// ---------------------------------------------------------------------------
__global__ void __launch_bounds__(256) mean_kernel(const float* __restrict__ x) {
    int plane = blockIdx.x;
    const float4* xp = (const float4*)(x + (size_t)plane * HW);
    int tid = threadIdx.x;
    float s = 0.f;
#pragma unroll
    for (int k = 0; k < 16; k++) {
        float4 v = xp[tid + k * 256];
        s += (v.x + v.y) + (v.z + v.w);
    }
#pragma unroll
    for (int o = 16; o; o >>= 1) s += __shfl_xor_sync(0xffffffffu, s, o);
    __shared__ float red[8];
    if ((tid & 31) == 0) red[tid >> 5] = s;
    __syncthreads();
    if (tid == 0) {
        float t = 0.f;
#pragma unroll
        for (int i = 0; i < 8; i++) t += red[i];
        g_p[plane] = t * (1.0f / 16384.0f);
    }
}

// ---------------------------------------------------------------------------
// K2 (fused): h = leaky(p @ w1^T); a = sigmoid(h @ w2^T). One block per batch.
// ---------------------------------------------------------------------------
__global__ void __launch_bounds__(256) attn_kernel(const float* __restrict__ w1,
                                                    const float* __restrict__ w2) {
    int b = blockIdx.x;
    __shared__ float ps[256];
    __shared__ float hs[64];
    int tid = threadIdx.x;
    ps[tid] = g_p[b * 256 + tid];
    __syncthreads();
    {
        int j = tid >> 2, part = tid & 3;
        const float* wr = w1 + j * 256 + part * 64;
        const float* pr = ps + part * 64;
        float s = 0.f;
#pragma unroll
        for (int c = 0; c < 64; c++) s = fmaf(pr[c], wr[c], s);
        s += __shfl_xor_sync(0xffffffffu, s, 1);
        s += __shfl_xor_sync(0xffffffffu, s, 2);
        if (part == 0) hs[j] = (s > 0.f) ? s : 0.01f * s;
    }
    __syncthreads();
    {
        const float* wr = w2 + tid * 64;
        float s = 0.f;
#pragma unroll
        for (int j = 0; j < 64; j++) s = fmaf(hs[j], wr[j], s);
        g_a[b * 256 + tid] = 1.0f / (1.0f + expf(-s));
    }
}

// ---------------------------------------------------------------------------
// 6-float row segment load (float4 + float2, both aligned)
// ---------------------------------------------------------------------------
__device__ __forceinline__ void ldrow(float* e, const float* p) {
    float4 q = *(const float4*)p;
    float2 t = *(const float2*)(p + 4);
    e[0] = q.x; e[1] = q.y; e[2] = q.z; e[3] = q.w; e[4] = t.x; e[5] = t.y;
}

// ---------------------------------------------------------------------------
// K3: per-plane fused scale -> depthwise 3x3 conv (+bias) -> InstanceNorm ->
// leaky_relu. One block per (b,c) plane. Conv outputs are NOT stored:
// pass 1 computes conv+stats, pass 2 RECOMPUTES the conv and normalizes.
// Both passes are read-only over the smem tile (no in-loop barriers).
// Rolling 3-row window: one new 6-float row load per output row.
// ---------------------------------------------------------------------------
__global__ void __launch_bounds__(256, 3) main_kernel(const float* __restrict__ x,
                                                       const float* __restrict__ rw,
                                                       const float* __restrict__ rb,
                                                       float* __restrict__ out) {
    extern __shared__ float sm[];
    int bc = (NPLANES - 1) - blockIdx.x;   // reverse order: ride mean_kernel's L2 tail
    int c = bc & 255;
    int tid = threadIdx.x;
    float a = g_a[bc];

    // Zero only the halo (top/bottom rows, left col, col 129)
    if (tid < 132) { sm[tid] = 0.f; sm[129 * SMS + tid] = 0.f; }
    if (tid < 130) { sm[tid * SMS] = 0.f; sm[tid * SMS + 129] = 0.f; }

    // Load plane (float4) scaled by attention, into smem at (+1,+1) offset
    const float4* xp = (const float4*)(x + (size_t)bc * HW);
#pragma unroll
    for (int k = 0; k < 16; k++) {
        int fi = tid + k * 256;
        float4 v = xp[fi];
        int row = fi >> 5;
        int col = (fi & 31) * 4;
        float* d = sm + (row + 1) * SMS + col + 1;
        d[0] = v.x * a; d[1] = v.y * a; d[2] = v.z * a; d[3] = v.w * a;
    }

    float w[9];
#pragma unroll
    for (int i = 0; i < 9; i++) w[i] = rw[c * 9 + i];
    float bias = rb[c];
    __syncthreads();

    // Strip assignment: cg = 4-col group, rs = 16-row segment; warp = one row band
    int cg = tid & 31, rseg = tid >> 5;
    int c0 = cg * 4;
    int R0 = rseg * 16;
    const float* tb = sm + R0 * SMS + c0;   // tile row R0 (= input row R0-1 / halo)

    // ---- Pass 1: conv + stats (rolling window) ----
    float e[3][6];
    ldrow(e[0], tb);
    ldrow(e[1], tb + SMS);
    float ssum = 0.f, ssq = 0.f;
#pragma unroll
    for (int i = 0; i < 16; i++) {
        ldrow(e[(i + 2) % 3], tb + (i + 2) * SMS);
        const float* et = e[i % 3];
        const float* em = e[(i + 1) % 3];
        const float* eb = e[(i + 2) % 3];
#pragma unroll
        for (int j = 0; j < 4; j++) {
            float s = bias;
            s = fmaf(et[j], w[0], s); s = fmaf(et[j+1], w[1], s); s = fmaf(et[j+2], w[2], s);
            s = fmaf(em[j], w[3], s); s = fmaf(em[j+1], w[4], s); s = fmaf(em[j+2], w[5], s);
            s = fmaf(eb[j], w[6], s); s = fmaf(eb[j+1], w[7], s); s = fmaf(eb[j+2], w[8], s);
            ssum += s;
            ssq = fmaf(s, s, ssq);
        }
    }

    // Block reduction of sum / sumsq
#pragma unroll
    for (int o = 16; o; o >>= 1) {
        ssum += __shfl_xor_sync(0xffffffffu, ssum, o);
        ssq  += __shfl_xor_sync(0xffffffffu, ssq, o);
    }
    __shared__ float r1[8], r2[8];
    __shared__ float s_mu, s_rs;
    if ((tid & 31) == 0) { r1[tid >> 5] = ssum; r2[tid >> 5] = ssq; }
    __syncthreads();
    if (tid == 0) {
        float t1 = 0.f, t2 = 0.f;
#pragma unroll
        for (int i = 0; i < 8; i++) { t1 += r1[i]; t2 += r2[i]; }
        float mu = t1 * (1.0f / 16384.0f);
        float var = t2 * (1.0f / 16384.0f) - mu * mu;
        s_mu = mu;
        s_rs = rsqrtf(var + 1e-5f);
    }
    __syncthreads();
    float mu = s_mu, rstd = s_rs;

    // ---- Pass 2: recompute conv, normalize + leaky relu, coalesced stores ----
    float4* op = (float4*)(out + (size_t)bc * HW);
    ldrow(e[0], tb);
    ldrow(e[1], tb + SMS);
#pragma unroll
    for (int i = 0; i < 16; i++) {
        ldrow(e[(i + 2) % 3], tb + (i + 2) * SMS);
        const float* et = e[i % 3];
        const float* em = e[(i + 1) % 3];
        const float* eb = e[(i + 2) % 3];
        float4 v;
        float* vp = (float*)&v;
#pragma unroll
        for (int j = 0; j < 4; j++) {
            float s = bias;
            s = fmaf(et[j], w[0], s); s = fmaf(et[j+1], w[1], s); s = fmaf(et[j+2], w[2], s);
            s = fmaf(em[j], w[3], s); s = fmaf(em[j+1], w[4], s); s = fmaf(em[j+2], w[5], s);
            s = fmaf(eb[j], w[6], s); s = fmaf(eb[j+1], w[7], s); s = fmaf(eb[j+2], w[8], s);
            float t = (s - mu) * rstd;
            vp[j] = (t > 0.f) ? t : 0.01f * t;
        }
        op[(R0 + i) * 32 + cg] = v;   // warp = same row, lanes consecutive: 512B stores
    }
}

// ---------------------------------------------------------------------------
extern "C" void kernel_launch(void* const* d_in, const int* in_sizes, int n_in,
                              void* d_out, int out_size) {
    const float* x  = (const float*)d_in[0];
    const float* w1 = (const float*)d_in[1];   // [64, 256]
    const float* w2 = (const float*)d_in[2];   // [256, 64]
    const float* rw = (const float*)d_in[3];   // [256, 1, 3, 3]
    const float* rb = (const float*)d_in[4];   // [256]
    float* out = (float*)d_out;

    cudaFuncSetAttribute(main_kernel, cudaFuncAttributeMaxDynamicSharedMemorySize,
                         SM_FLOATS * (int)sizeof(float));

    mean_kernel<<<NPLANES, 256>>>(x);
    attn_kernel<<<8, 256>>>(w1, w2);
    main_kernel<<<NPLANES, 256, SM_FLOATS * sizeof(float)>>>(x, rw, rb, out);
}

// round 6
// speedup vs baseline: 1.4581x; 1.2247x over previous
#include <cuda_runtime.h>
#include <math.h>

// Problem constants: x[8, 256, 128, 128] fp32
#define NPLANES 2048
#define HW      16384
#define FULL    0xffffffffu

// Scratch (no allocations allowed)
__device__ float g_p[NPLANES];    // per-plane mean of x
__device__ float g_cs[NPLANES];   // sum of conv(x) (unscaled, no bias)
__device__ float g_cq[NPLANES];   // sumsq of conv(x)
__device__ float g_a[NPLANES];    // sigmoid attention scales

// Build a 6-float window row from an aligned float4 + warp shuffles.
// e = inputs cols [c0-1 .. c0+4] for lane's c0 = lane*4. Plane edges -> 0.
__device__ __forceinline__ void mkrow(float* e, float4 v, int lane) {
    float lft = __shfl_up_sync(FULL, v.w, 1);
    float rgt = __shfl_down_sync(FULL, v.x, 1);
    if (lane == 0)  lft = 0.f;
    if (lane == 31) rgt = 0.f;
    e[0] = lft; e[1] = v.x; e[2] = v.y; e[3] = v.z; e[4] = v.w; e[5] = rgt;
}

__device__ __forceinline__ float conv4(const float* et, const float* em,
                                        const float* eb, const float* w,
                                        float init, int j) {
    float s = init;
    s = fmaf(et[j], w[0], s); s = fmaf(et[j+1], w[1], s); s = fmaf(et[j+2], w[2], s);
    s = fmaf(em[j], w[3], s); s = fmaf(em[j+1], w[4], s); s = fmaf(em[j+2], w[5], s);
    s = fmaf(eb[j], w[6], s); s = fmaf(eb[j+1], w[7], s); s = fmaf(eb[j+2], w[8], s);
    return s;
}

// ---------------------------------------------------------------------------
// K1: one block per plane. Single read of x producing: plane mean (for the
// attention pool) AND sum/sumsq of conv(x) (unscaled, no bias) via a
// register-rolling shuffle-conv. No smem tile, no tile barriers.
// Warp = 32 lanes x 4 cols = full 128-col row; warp w owns rows [16w, 16w+16).
// ---------------------------------------------------------------------------
__global__ void __launch_bounds__(256) stats_kernel(const float* __restrict__ x,
                                                     const float* __restrict__ rw) {
    int plane = blockIdx.x;
    int c = plane & 255;
    int tid = threadIdx.x, lane = tid & 31, rseg = tid >> 5;
    int R0 = rseg * 16;
    const float4* xp = (const float4*)(x + (size_t)plane * HW);

    float w[9];
#pragma unroll
    for (int i = 0; i < 9; i++) w[i] = rw[c * 9 + i];

    float psum = 0.f, csum = 0.f, csq = 0.f;
    float e[3][6];
    // preload rows R0-1 and R0
    {
        float4 v = (R0 == 0) ? make_float4(0.f,0.f,0.f,0.f) : xp[(R0 - 1) * 32 + lane];
        mkrow(e[0], v, lane);
        float4 u = xp[R0 * 32 + lane];
        psum += (u.x + u.y) + (u.z + u.w);
        mkrow(e[1], u, lane);
    }
#pragma unroll
    for (int i = 0; i < 16; i++) {
        int rn = R0 + i + 1;
        float4 v = (rn > 127) ? make_float4(0.f,0.f,0.f,0.f) : xp[rn * 32 + lane];
        if (i < 15) psum += (v.x + v.y) + (v.z + v.w);   // own rows only
        mkrow(e[(i + 2) % 3], v, lane);
        const float* et = e[i % 3];
        const float* em = e[(i + 1) % 3];
        const float* eb = e[(i + 2) % 3];
#pragma unroll
        for (int j = 0; j < 4; j++) {
            float s = conv4(et, em, eb, w, 0.f, j);
            csum += s;
            csq = fmaf(s, s, csq);
        }
    }

    // Block reduction of psum / csum / csq
#pragma unroll
    for (int o = 16; o; o >>= 1) {
        psum += __shfl_xor_sync(FULL, psum, o);
        csum += __shfl_xor_sync(FULL, csum, o);
        csq  += __shfl_xor_sync(FULL, csq,  o);
    }
    __shared__ float r0[8], r1[8], r2[8];
    if (lane == 0) { r0[rseg] = psum; r1[rseg] = csum; r2[rseg] = csq; }
    __syncthreads();
    if (tid == 0) {
        float t0 = 0.f, t1 = 0.f, t2 = 0.f;
#pragma unroll
        for (int i = 0; i < 8; i++) { t0 += r0[i]; t1 += r1[i]; t2 += r2[i]; }
        g_p[plane]  = t0 * (1.0f / 16384.0f);
        g_cs[plane] = t1;
        g_cq[plane] = t2;
    }
}

// ---------------------------------------------------------------------------
// K2 (fused SE attention): h = leaky(p @ w1^T); a = sigmoid(h @ w2^T).
// ---------------------------------------------------------------------------
__global__ void __launch_bounds__(256) attn_kernel(const float* __restrict__ w1,
                                                    const float* __restrict__ w2) {
    int b = blockIdx.x;
    __shared__ float ps[256];
    __shared__ float hs[64];
    int tid = threadIdx.x;
    ps[tid] = g_p[b * 256 + tid];
    __syncthreads();
    {
        int j = tid >> 2, part = tid & 3;
        const float* wr = w1 + j * 256 + part * 64;
        const float* pr = ps + part * 64;
        float s = 0.f;
#pragma unroll
        for (int cc = 0; cc < 64; cc++) s = fmaf(pr[cc], wr[cc], s);
        s += __shfl_xor_sync(FULL, s, 1);
        s += __shfl_xor_sync(FULL, s, 2);
        if (part == 0) hs[j] = (s > 0.f) ? s : 0.01f * s;
    }
    __syncthreads();
    {
        const float* wr = w2 + tid * 64;
        float s = 0.f;
#pragma unroll
        for (int j = 0; j < 64; j++) s = fmaf(hs[j], wr[j], s);
        g_a[b * 256 + tid] = 1.0f / (1.0f + expf(-s));
    }
}

// ---------------------------------------------------------------------------
// K3: one block per plane, reverse order (ride K1's L2 tail). SINGLE conv
// pass: y = conv(a*x) + b computed with a-prescaled weights; InstanceNorm
// stats derived analytically from K1's unscaled conv stats:
//   mu_y = a*mu_c + b,   var_y = a^2*var_c.
// Normalize + leaky, coalesced float4 stores. No smem tile, no reductions.
// ---------------------------------------------------------------------------
__global__ void __launch_bounds__(256) main_kernel(const float* __restrict__ x,
                                                    const float* __restrict__ rw,
                                                    const float* __restrict__ rb,
                                                    float* __restrict__ out) {
    int bc = (NPLANES - 1) - blockIdx.x;
    int c = bc & 255;
    int tid = threadIdx.x, lane = tid & 31, rseg = tid >> 5;
    int R0 = rseg * 16;
    const float4* xp = (const float4*)(x + (size_t)bc * HW);
    float4* op = (float4*)(out + (size_t)bc * HW);

    float a = g_a[bc];
    float bias = rb[c];
    float mu_c  = g_cs[bc] * (1.0f / 16384.0f);
    float var_c = g_cq[bc] * (1.0f / 16384.0f) - mu_c * mu_c;
    float mu   = a * mu_c + bias;
    float rstd = rsqrtf(a * a * var_c + 1e-5f);

    float w[9];
#pragma unroll
    for (int i = 0; i < 9; i++) w[i] = a * rw[c * 9 + i];

    float e[3][6];
    {
        float4 v = (R0 == 0) ? make_float4(0.f,0.f,0.f,0.f) : xp[(R0 - 1) * 32 + lane];
        mkrow(e[0], v, lane);
        float4 u = xp[R0 * 32 + lane];
        mkrow(e[1], u, lane);
    }
#pragma unroll
    for (int i = 0; i < 16; i++) {
        int rn = R0 + i + 1;
        float4 v = (rn > 127) ? make_float4(0.f,0.f,0.f,0.f) : xp[rn * 32 + lane];
        mkrow(e[(i + 2) % 3], v, lane);
        const float* et = e[i % 3];
        const float* em = e[(i + 1) % 3];
        const float* eb = e[(i + 2) % 3];
        float4 o;
        float* opn = (float*)&o;
#pragma unroll
        for (int j = 0; j < 4; j++) {
            float s = conv4(et, em, eb, w, bias, j);
            float t = (s - mu) * rstd;
            opn[j] = (t > 0.f) ? t : 0.01f * t;
        }
        op[(R0 + i) * 32 + lane] = o;
    }
}

// ---------------------------------------------------------------------------
extern "C" void kernel_launch(void* const* d_in, const int* in_sizes, int n_in,
                              void* d_out, int out_size) {
    const float* x  = (const float*)d_in[0];
    const float* w1 = (const float*)d_in[1];   // [64, 256]
    const float* w2 = (const float*)d_in[2];   // [256, 64]
    const float* rw = (const float*)d_in[3];   // [256, 1, 3, 3]
    const float* rb = (const float*)d_in[4];   // [256]
    float* out = (float*)d_out;

    stats_kernel<<<NPLANES, 256>>>(x, rw);
    attn_kernel<<<8, 256>>>(w1, w2);
    main_kernel<<<NPLANES, 256>>>(x, rw, rb, out);
}